// round 1
// baseline (speedup 1.0000x reference)
#include <cuda_runtime.h>
#include <math.h>

// Problem constants
#define BB   4
#define TT   4096
#define DD   1024
#define HH   16
#define DHH  64
#define NKV  32          // TT / 128 KV blocks

// Scratch (device globals: allocation-free rule)
__device__ float g_Q [BB*HH*TT*DHH];   // (b,h,t,d)   64MB
__device__ float g_KT[BB*HH*DHH*TT];   // (b,h,d,t)   64MB (transposed per head)
__device__ float g_V [BB*HH*TT*DHH];   // (b,h,t,d)   64MB
__device__ float g_O [BB*TT*DD];       // (b,t,D)     64MB

#define FMA4(acc, s, v)                       \
    acc.x = fmaf((s), (v).x, acc.x);          \
    acc.y = fmaf((s), (v).y, acc.y);          \
    acc.z = fmaf((s), (v).z, acc.z);          \
    acc.w = fmaf((s), (v).w, acc.w);

// ---------------------------------------------------------------------------
// C = A(M=16384,K=1024) @ W(N=1024,K=1024)^T + bias, 128x128 tile, 256 thr.
// mode 0: C[m][n]                      (B,T,D)
// mode 1: head-split   -> out[(b*16+h)*T + t][dh]      (b,h,t,d)
// mode 2: head-split+T -> out[(b*16+h)*64 + dh][t]     (b,h,d,t)
// ---------------------------------------------------------------------------
__global__ __launch_bounds__(256, 2)
void gemm128(const float* __restrict__ A, const float* __restrict__ W,
             const float* __restrict__ bias, float* __restrict__ C, int mode)
{
    __shared__ float sA[128 * 16];   // [row][k]
    __shared__ float sB[16 * 128];   // [k][col]

    const int tid = threadIdx.x;
    const int tx = tid & 15, ty = tid >> 4;
    const int n0 = blockIdx.x * 128, m0 = blockIdx.y * 128;

    float acc[8][8];
#pragma unroll
    for (int i = 0; i < 8; i++)
#pragma unroll
        for (int j = 0; j < 8; j++) acc[i][j] = 0.f;

    for (int kt = 0; kt < 1024; kt += 16) {
#pragma unroll
        for (int rep = 0; rep < 2; rep++) {
            int idx = tid + rep * 256;           // 0..511
            int r  = idx >> 2;
            int k4 = idx & 3;
            float4 av = *(const float4*)&A[(size_t)(m0 + r) * 1024 + kt + k4 * 4];
            *(float4*)&sA[r * 16 + k4 * 4] = av;
            float4 wv = *(const float4*)&W[(size_t)(n0 + r) * 1024 + kt + k4 * 4];
            sB[(k4 * 4 + 0) * 128 + r] = wv.x;
            sB[(k4 * 4 + 1) * 128 + r] = wv.y;
            sB[(k4 * 4 + 2) * 128 + r] = wv.z;
            sB[(k4 * 4 + 3) * 128 + r] = wv.w;
        }
        __syncthreads();
#pragma unroll
        for (int kk = 0; kk < 16; kk++) {
            float b[8];
            float4 b0 = *(const float4*)&sB[kk * 128 + tx * 8];
            float4 b1 = *(const float4*)&sB[kk * 128 + tx * 8 + 4];
            b[0] = b0.x; b[1] = b0.y; b[2] = b0.z; b[3] = b0.w;
            b[4] = b1.x; b[5] = b1.y; b[6] = b1.z; b[7] = b1.w;
#pragma unroll
            for (int i = 0; i < 8; i++) {
                float a = sA[(ty * 8 + i) * 16 + kk];
#pragma unroll
                for (int j = 0; j < 8; j++) acc[i][j] = fmaf(a, b[j], acc[i][j]);
            }
        }
        __syncthreads();
    }

    const int n_base = n0 + tx * 8;
    const int m_base = m0 + ty * 8;
    float bb[8];
#pragma unroll
    for (int j = 0; j < 8; j++) bb[j] = bias[n_base + j];

    if (mode == 0) {
#pragma unroll
        for (int i = 0; i < 8; i++) {
            float* p = &C[(size_t)(m_base + i) * 1024 + n_base];
            *(float4*)(p)     = make_float4(acc[i][0]+bb[0], acc[i][1]+bb[1], acc[i][2]+bb[2], acc[i][3]+bb[3]);
            *(float4*)(p + 4) = make_float4(acc[i][4]+bb[4], acc[i][5]+bb[5], acc[i][6]+bb[6], acc[i][7]+bb[7]);
        }
    } else if (mode == 1) {
        const int h = n_base >> 6, dcol = n_base & 63;
#pragma unroll
        for (int i = 0; i < 8; i++) {
            int m = m_base + i;
            int b = m >> 12, t = m & 4095;
            float* p = &C[(((size_t)(b * 16 + h) * 4096 + t) * 64) + dcol];
            *(float4*)(p)     = make_float4(acc[i][0]+bb[0], acc[i][1]+bb[1], acc[i][2]+bb[2], acc[i][3]+bb[3]);
            *(float4*)(p + 4) = make_float4(acc[i][4]+bb[4], acc[i][5]+bb[5], acc[i][6]+bb[6], acc[i][7]+bb[7]);
        }
    } else {
        const int h = n_base >> 6, dcol = n_base & 63;
        const int b = m_base >> 12, t0 = m_base & 4095;
#pragma unroll
        for (int j = 0; j < 8; j++) {
            float bj = bb[j];
            size_t base = ((size_t)(b * 16 + h) * 64 + (dcol + j)) * 4096 + t0;
            *(float4*)&C[base]     = make_float4(acc[0][j]+bj, acc[1][j]+bj, acc[2][j]+bj, acc[3][j]+bj);
            *(float4*)&C[base + 4] = make_float4(acc[4][j]+bj, acc[5][j]+bj, acc[6][j]+bj, acc[7][j]+bj);
        }
    }
}

// ---------------------------------------------------------------------------
// Streaming-softmax attention, replicating the reference's *unrescaled-O*
// semantics. One CTA = 64 query rows of one (b,h). 256 threads.
// smem: Q(64x64) + KT(64x128) + Vhalf(64x64) + S(64x128) + L(64)
// ---------------------------------------------------------------------------
#define SMEM_ATTN ((4096 + 8192 + 4096 + 8192 + 64) * 4)

__global__ __launch_bounds__(256, 2)
void attn_kernel(const float* __restrict__ Qh, const float* __restrict__ KTh,
                 const float* __restrict__ Vh, float* __restrict__ O)
{
    extern __shared__ float smem[];
    float* sQ  = smem;              // 64 x 64
    float* sKT = sQ  + 4096;        // 64(d) x 128(c)
    float* sV  = sKT + 8192;        // 64(k) x 64(d)  (half of BKV)
    float* sS  = sV  + 4096;        // 64 x 128
    float* sL  = sS  + 8192;        // 64

    const int tid  = threadIdx.x;
    const int lane = tid & 31, warp = tid >> 5;
    const int bh = blockIdx.y;
    const int q0 = blockIdx.x * 64;

    const float* Qp = Qh  + ((size_t)bh * TT + q0) * 64;
    const float* Kp = KTh + (size_t)bh * 64 * TT;
    const float* Vp = Vh  + (size_t)bh * TT * 64;

    // Q tile: contiguous 16KB
#pragma unroll
    for (int i = 0; i < 4; i++)
        ((float4*)sQ)[tid + i * 256] = ((const float4*)Qp)[tid + i * 256];

    const int r0  = warp * 8;          // S rows for this warp
    const int c0  = lane * 4;          // S cols for this lane
    const int rg  = tid >> 4, cg = tid & 15;
    const int r0p = rg * 4, d0 = cg * 4;   // PV rows / cols

    float m_arr[8], l_arr[8];
#pragma unroll
    for (int i = 0; i < 8; i++) { m_arr[i] = -INFINITY; l_arr[i] = 0.f; }
    float4 oacc[4];
#pragma unroll
    for (int i = 0; i < 4; i++) oacc[i] = make_float4(0.f, 0.f, 0.f, 0.f);

    for (int j = 0; j < NKV; j++) {
        __syncthreads();
        // K_j (already transposed in gmem) + V half0
        {
            const float* kp = Kp + j * 128;
#pragma unroll
            for (int it = 0; it < 8; it++) {
                int idx = tid + it * 256;              // 0..2047
                int d = idx >> 5, c4 = idx & 31;
                *(float4*)&sKT[d * 128 + c4 * 4] =
                    *(const float4*)(kp + (size_t)d * TT + c4 * 4);
            }
            const float* vp = Vp + (size_t)(j * 128) * 64;
#pragma unroll
            for (int it = 0; it < 4; it++)
                ((float4*)sV)[tid + it * 256] = ((const float4*)vp)[tid + it * 256];
        }
        __syncthreads();

        // S = Q @ K^T  (each thread: 8 rows x 4 cols)
        float4 sacc[8];
#pragma unroll
        for (int i = 0; i < 8; i++) sacc[i] = make_float4(0.f, 0.f, 0.f, 0.f);
#pragma unroll
        for (int d4 = 0; d4 < 16; d4++) {
            float4 k0 = *(const float4*)&sKT[(d4 * 4 + 0) * 128 + c0];
            float4 k1 = *(const float4*)&sKT[(d4 * 4 + 1) * 128 + c0];
            float4 k2 = *(const float4*)&sKT[(d4 * 4 + 2) * 128 + c0];
            float4 k3 = *(const float4*)&sKT[(d4 * 4 + 3) * 128 + c0];
#pragma unroll
            for (int i = 0; i < 8; i++) {
                float4 q = *(const float4*)&sQ[(r0 + i) * 64 + d4 * 4];
                FMA4(sacc[i], q.x, k0);
                FMA4(sacc[i], q.y, k1);
                FMA4(sacc[i], q.z, k2);
                FMA4(sacc[i], q.w, k3);
            }
        }

        // Streaming softmax update (reference semantics: O NOT rescaled)
#pragma unroll
        for (int i = 0; i < 8; i++) {
            float4 v = sacc[i];
            float mx = fmaxf(fmaxf(v.x, v.y), fmaxf(v.z, v.w));
#pragma unroll
            for (int off = 16; off; off >>= 1)
                mx = fmaxf(mx, __shfl_xor_sync(0xffffffffu, mx, off));
            float mold = m_arr[i];
            float mn = fmaxf(mold, mx);
            v.x = __expf(v.x - mn); v.y = __expf(v.y - mn);
            v.z = __expf(v.z - mn); v.w = __expf(v.w - mn);
            float sm = v.x + v.y + v.z + v.w;
#pragma unroll
            for (int off = 16; off; off >>= 1)
                sm += __shfl_xor_sync(0xffffffffu, sm, off);
            l_arr[i] = __expf(mold - mn) * l_arr[i] + sm;
            m_arr[i] = mn;
            *(float4*)&sS[(r0 + i) * 128 + c0] = v;
        }
        __syncthreads();

        // O += P @ V  (half 0: k = 0..63)
#pragma unroll
        for (int kq = 0; kq < 16; kq++) {
            float4 v0 = *(const float4*)&sV[(kq * 4 + 0) * 64 + d0];
            float4 v1 = *(const float4*)&sV[(kq * 4 + 1) * 64 + d0];
            float4 v2 = *(const float4*)&sV[(kq * 4 + 2) * 64 + d0];
            float4 v3 = *(const float4*)&sV[(kq * 4 + 3) * 64 + d0];
#pragma unroll
            for (int i = 0; i < 4; i++) {
                float4 p = *(const float4*)&sS[(r0p + i) * 128 + kq * 4];
                FMA4(oacc[i], p.x, v0);
                FMA4(oacc[i], p.y, v1);
                FMA4(oacc[i], p.z, v2);
                FMA4(oacc[i], p.w, v3);
            }
        }
        __syncthreads();
        // V half1
        {
            const float* vp = Vp + (size_t)(j * 128 + 64) * 64;
#pragma unroll
            for (int it = 0; it < 4; it++)
                ((float4*)sV)[tid + it * 256] = ((const float4*)vp)[tid + it * 256];
        }
        __syncthreads();
        // half 1: k = 64..127
#pragma unroll
        for (int kq = 0; kq < 16; kq++) {
            float4 v0 = *(const float4*)&sV[(kq * 4 + 0) * 64 + d0];
            float4 v1 = *(const float4*)&sV[(kq * 4 + 1) * 64 + d0];
            float4 v2 = *(const float4*)&sV[(kq * 4 + 2) * 64 + d0];
            float4 v3 = *(const float4*)&sV[(kq * 4 + 3) * 64 + d0];
#pragma unroll
            for (int i = 0; i < 4; i++) {
                float4 p = *(const float4*)&sS[(r0p + i) * 128 + 64 + kq * 4];
                FMA4(oacc[i], p.x, v0);
                FMA4(oacc[i], p.y, v1);
                FMA4(oacc[i], p.z, v2);
                FMA4(oacc[i], p.w, v3);
            }
        }
    }

    // publish L (values are warp-uniform), then normalize + write O in (B,T,D)
    if (lane == 0) {
#pragma unroll
        for (int i = 0; i < 8; i++) sL[r0 + i] = l_arr[i];
    }
    __syncthreads();

    const int b = bh >> 4, h = bh & 15;
#pragma unroll
    for (int i = 0; i < 4; i++) {
        int r = r0p + i;
        float inv = 1.f / sL[r];
        float4 o = oacc[i];
        o.x *= inv; o.y *= inv; o.z *= inv; o.w *= inv;
        *(float4*)&O[((size_t)(b * 4096 + q0 + r)) * 1024 + h * 64 + d0] = o;
    }
}

// ---------------------------------------------------------------------------
extern "C" void kernel_launch(void* const* d_in, const int* in_sizes, int n_in,
                              void* d_out, int out_size)
{
    const float* x  = (const float*)d_in[0];
    const float* wq = (const float*)d_in[1];
    const float* bq = (const float*)d_in[2];
    const float* wk = (const float*)d_in[3];
    const float* bk = (const float*)d_in[4];
    const float* wv = (const float*)d_in[5];
    const float* bv = (const float*)d_in[6];
    const float* wo = (const float*)d_in[7];
    const float* bo = (const float*)d_in[8];
    float* out = (float*)d_out;

    float *gQ, *gKT, *gV, *gO;
    cudaGetSymbolAddress((void**)&gQ,  g_Q);
    cudaGetSymbolAddress((void**)&gKT, g_KT);
    cudaGetSymbolAddress((void**)&gV,  g_V);
    cudaGetSymbolAddress((void**)&gO,  g_O);

    cudaFuncSetAttribute(attn_kernel,
                         cudaFuncAttributeMaxDynamicSharedMemorySize, SMEM_ATTN);

    dim3 gg(8, 128);   // N tiles x M tiles
    gemm128<<<gg, 256>>>(x, wq, bq, gQ, 1);   // Q  -> (b,h,t,d)
    gemm128<<<gg, 256>>>(x, wk, bk, gKT, 2);  // K  -> (b,h,d,t) transposed
    gemm128<<<gg, 256>>>(x, wv, bv, gV, 1);   // V  -> (b,h,t,d)

    attn_kernel<<<dim3(64, 64), 256, SMEM_ATTN>>>(gQ, gKT, gV, gO);

    gemm128<<<gg, 256>>>(gO, wo, bo, out, 0); // final projection -> (B,T,D)
}

// round 3
// speedup vs baseline: 1.1562x; 1.1562x over previous
#include <cuda_runtime.h>
#include <cuda_bf16.h>
#include <math.h>
#include <cstdint>

// Problem constants
#define BB   4
#define TT   4096
#define DD   1024
#define HH   16
#define NKV  32          // TT / 128 KV blocks

// Scratch (device globals: allocation-free rule)
__device__ float g_Q [BB*HH*TT*64];   // (b,h,t,d)
__device__ float g_K [BB*HH*TT*64];   // (b,h,t,d)
__device__ float g_VT[BB*HH*64*TT];   // (b,h,d,t)  V transposed per head
__device__ float g_O [BB*TT*DD];      // (b,t,D)

// ===========================================================================
// fp32 projection GEMM (proven in R1)
// ===========================================================================
__global__ __launch_bounds__(256, 2)
void gemm128(const float* __restrict__ A, const float* __restrict__ W,
             const float* __restrict__ bias, float* __restrict__ C, int mode)
{
    __shared__ float sA[128 * 16];
    __shared__ float sB[16 * 128];

    const int tid = threadIdx.x;
    const int tx = tid & 15, ty = tid >> 4;
    const int n0 = blockIdx.x * 128, m0 = blockIdx.y * 128;

    float acc[8][8];
#pragma unroll
    for (int i = 0; i < 8; i++)
#pragma unroll
        for (int j = 0; j < 8; j++) acc[i][j] = 0.f;

    for (int kt = 0; kt < 1024; kt += 16) {
#pragma unroll
        for (int rep = 0; rep < 2; rep++) {
            int idx = tid + rep * 256;
            int r  = idx >> 2;
            int k4 = idx & 3;
            float4 av = *(const float4*)&A[(size_t)(m0 + r) * 1024 + kt + k4 * 4];
            *(float4*)&sA[r * 16 + k4 * 4] = av;
            float4 wv = *(const float4*)&W[(size_t)(n0 + r) * 1024 + kt + k4 * 4];
            sB[(k4 * 4 + 0) * 128 + r] = wv.x;
            sB[(k4 * 4 + 1) * 128 + r] = wv.y;
            sB[(k4 * 4 + 2) * 128 + r] = wv.z;
            sB[(k4 * 4 + 3) * 128 + r] = wv.w;
        }
        __syncthreads();
#pragma unroll
        for (int kk = 0; kk < 16; kk++) {
            float b[8];
            float4 b0 = *(const float4*)&sB[kk * 128 + tx * 8];
            float4 b1 = *(const float4*)&sB[kk * 128 + tx * 8 + 4];
            b[0] = b0.x; b[1] = b0.y; b[2] = b0.z; b[3] = b0.w;
            b[4] = b1.x; b[5] = b1.y; b[6] = b1.z; b[7] = b1.w;
#pragma unroll
            for (int i = 0; i < 8; i++) {
                float a = sA[(ty * 8 + i) * 16 + kk];
#pragma unroll
                for (int j = 0; j < 8; j++) acc[i][j] = fmaf(a, b[j], acc[i][j]);
            }
        }
        __syncthreads();
    }

    const int n_base = n0 + tx * 8;
    const int m_base = m0 + ty * 8;
    float bb[8];
#pragma unroll
    for (int j = 0; j < 8; j++) bb[j] = bias[n_base + j];

    if (mode == 0) {
#pragma unroll
        for (int i = 0; i < 8; i++) {
            float* p = &C[(size_t)(m_base + i) * 1024 + n_base];
            *(float4*)(p)     = make_float4(acc[i][0]+bb[0], acc[i][1]+bb[1], acc[i][2]+bb[2], acc[i][3]+bb[3]);
            *(float4*)(p + 4) = make_float4(acc[i][4]+bb[4], acc[i][5]+bb[5], acc[i][6]+bb[6], acc[i][7]+bb[7]);
        }
    } else if (mode == 1) {
        const int h = n_base >> 6, dcol = n_base & 63;
#pragma unroll
        for (int i = 0; i < 8; i++) {
            int m = m_base + i;
            int b = m >> 12, t = m & 4095;
            float* p = &C[(((size_t)(b * 16 + h) * 4096 + t) * 64) + dcol];
            *(float4*)(p)     = make_float4(acc[i][0]+bb[0], acc[i][1]+bb[1], acc[i][2]+bb[2], acc[i][3]+bb[3]);
            *(float4*)(p + 4) = make_float4(acc[i][4]+bb[4], acc[i][5]+bb[5], acc[i][6]+bb[6], acc[i][7]+bb[7]);
        }
    } else {
        const int h = n_base >> 6, dcol = n_base & 63;
        const int b = m_base >> 12, t0 = m_base & 4095;
#pragma unroll
        for (int j = 0; j < 8; j++) {
            float bj = bb[j];
            size_t base = ((size_t)(b * 16 + h) * 64 + (dcol + j)) * 4096 + t0;
            *(float4*)&C[base]     = make_float4(acc[0][j]+bj, acc[1][j]+bj, acc[2][j]+bj, acc[3][j]+bj);
            *(float4*)&C[base + 4] = make_float4(acc[4][j]+bj, acc[5][j]+bj, acc[6][j]+bj, acc[7][j]+bj);
        }
    }
}

// ===========================================================================
// mma.sync bf16 attention (hi/lo split). One CTA = 128 q rows of one (b,h).
// 8 warps, each owns a 16x128 S stripe. P stays in registers (C-frag -> A-frag
// register identity for m16n8k16). Reference semantics: O never rescaled.
// ===========================================================================
// smem word offsets (uint32 units). K rows padded 32->36 words, VT 64->68.
#define KHI_W 0
#define KLO_W 4608          // 128*36
#define VHI_W 9216
#define VLO_W 13568         // + 64*68
#define SMEM_W 17920
#define SMEM_ATTN_B (SMEM_W * 4)

__device__ __forceinline__ void mma16816(float4& d,
    uint32_t a0, uint32_t a1, uint32_t a2, uint32_t a3,
    uint32_t b0, uint32_t b1)
{
    asm volatile(
        "mma.sync.aligned.m16n8k16.row.col.f32.bf16.bf16.f32 "
        "{%0,%1,%2,%3}, {%4,%5,%6,%7}, {%8,%9}, {%0,%1,%2,%3};"
        : "+f"(d.x), "+f"(d.y), "+f"(d.z), "+f"(d.w)
        : "r"(a0), "r"(a1), "r"(a2), "r"(a3), "r"(b0), "r"(b1));
}

__device__ __forceinline__ uint32_t pack_hi(float a, float b) {
    __nv_bfloat162 t = __floats2bfloat162_rn(a, b);
    return *(uint32_t*)&t;
}
__device__ __forceinline__ uint32_t pack_lo(float a, float b, uint32_t hi) {
    __nv_bfloat162 h = *(__nv_bfloat162*)&hi;
    __nv_bfloat162 t = __floats2bfloat162_rn(a - __bfloat162float(h.x),
                                             b - __bfloat162float(h.y));
    return *(uint32_t*)&t;
}

__global__ __launch_bounds__(256, 1)
void attn_mma(const float* __restrict__ Q, const float* __restrict__ K,
              const float* __restrict__ VT, float* __restrict__ O)
{
    extern __shared__ uint32_t sm[];
    const int tid  = threadIdx.x;
    const int lane = tid & 31, wid = tid >> 5;
    const int bh = blockIdx.y, q0 = blockIdx.x * 128;
    const int b = bh >> 4, h = bh & 15;

    const int r0 = lane >> 2;           // fragment row (0..7)
    const int c2 = (lane & 3) * 2;      // fragment col pair base

    // ---- Q fragments, hi/lo bf16, register-resident for the whole kernel ----
    // idx = ks*4 + ko*2 + ro  => a0,a1,a2,a3 = (ro0ko0, ro1ko0, ro0ko1, ro1ko1)
    uint32_t QH[16], QL[16];
    {
        const float* gq = Q + ((size_t)bh * TT + q0 + wid * 16) * 64;
#pragma unroll
        for (int ks = 0; ks < 4; ks++)
#pragma unroll
            for (int ko = 0; ko < 2; ko++)
#pragma unroll
                for (int ro = 0; ro < 2; ro++) {
                    float2 q = *(const float2*)(gq + (size_t)(r0 + 8 * ro) * 64
                                                + ks * 16 + ko * 8 + c2);
                    int idx = ks * 4 + ko * 2 + ro;
                    QH[idx] = pack_hi(q.x, q.y);
                    QL[idx] = pack_lo(q.x, q.y, QH[idx]);
                }
    }

    float4 Oacc[8];
#pragma unroll
    for (int i = 0; i < 8; i++) Oacc[i] = make_float4(0.f, 0.f, 0.f, 0.f);
    float m0 = -INFINITY, m1 = -INFINITY, l0 = 0.f, l1 = 0.f;

    const int kbase = (lane >> 2) * 36 + (lane & 3);   // K b-frag base word
    const int vbase = (lane >> 2) * 68 + (lane & 3);   // V b-frag base word

    for (int j = 0; j < NKV; j++) {
        __syncthreads();   // previous iteration done reading smem

        // ---- load + convert K (128x64) and VT (64x128) to hi/lo bf16 ----
        {
            const float* gk = K + ((size_t)bh * TT + j * 128) * 64;
#pragma unroll
            for (int it = 0; it < 8; it++) {
                int e = tid + it * 256;            // 0..2047 float4s
                int r = e >> 4, c4 = e & 15;
                float4 v = ((const float4*)gk)[e];
                int w = r * 36 + c4 * 2;
                uint32_t h0 = pack_hi(v.x, v.y), h1 = pack_hi(v.z, v.w);
                sm[KHI_W + w] = h0;           sm[KHI_W + w + 1] = h1;
                sm[KLO_W + w] = pack_lo(v.x, v.y, h0);
                sm[KLO_W + w + 1] = pack_lo(v.z, v.w, h1);
            }
            const float* gv = VT + (size_t)bh * 64 * TT + j * 128;
#pragma unroll
            for (int it = 0; it < 8; it++) {
                int e = tid + it * 256;            // 0..2047 float4s of 64x128
                int r = e >> 5, c4 = e & 31;
                float4 v = *(const float4*)(gv + (size_t)r * TT + c4 * 4);
                int w = r * 68 + c4 * 2;
                uint32_t h0 = pack_hi(v.x, v.y), h1 = pack_hi(v.z, v.w);
                sm[VHI_W + w] = h0;           sm[VHI_W + w + 1] = h1;
                sm[VLO_W + w] = pack_lo(v.x, v.y, h0);
                sm[VLO_W + w + 1] = pack_lo(v.z, v.w, h1);
            }
        }
        __syncthreads();

        // ---- S = Q K^T : 16 n-tiles x 4 k-steps x 3 split-terms ----
        float4 Sacc[16];
#pragma unroll
        for (int nt = 0; nt < 16; nt++) {
            float4 acc = make_float4(0.f, 0.f, 0.f, 0.f);
            int nb = nt * (8 * 36);
#pragma unroll
            for (int ks = 0; ks < 4; ks++) {
                int wA = kbase + nb + ks * 8;
                uint32_t bh0 = sm[KHI_W + wA], bh1 = sm[KHI_W + wA + 4];
                uint32_t bl0 = sm[KLO_W + wA], bl1 = sm[KLO_W + wA + 4];
                int q = ks * 4;
                mma16816(acc, QH[q], QH[q+1], QH[q+2], QH[q+3], bh0, bh1);
                mma16816(acc, QH[q], QH[q+1], QH[q+2], QH[q+3], bl0, bl1);
                mma16816(acc, QL[q], QL[q+1], QL[q+2], QL[q+3], bh0, bh1);
            }
            Sacc[nt] = acc;
        }

        // ---- streaming softmax (rows r0 and r0+8), all in registers ----
        float mx0 = -INFINITY, mx1 = -INFINITY;
#pragma unroll
        for (int nt = 0; nt < 16; nt++) {
            mx0 = fmaxf(mx0, fmaxf(Sacc[nt].x, Sacc[nt].y));
            mx1 = fmaxf(mx1, fmaxf(Sacc[nt].z, Sacc[nt].w));
        }
        mx0 = fmaxf(mx0, __shfl_xor_sync(0xffffffffu, mx0, 1));
        mx0 = fmaxf(mx0, __shfl_xor_sync(0xffffffffu, mx0, 2));
        mx1 = fmaxf(mx1, __shfl_xor_sync(0xffffffffu, mx1, 1));
        mx1 = fmaxf(mx1, __shfl_xor_sync(0xffffffffu, mx1, 2));
        float mn0 = fmaxf(m0, mx0), mn1 = fmaxf(m1, mx1);

        uint32_t PH01[16], PH23[16], PL01[16], PL23[16];
        float s0 = 0.f, s1 = 0.f;
#pragma unroll
        for (int nt = 0; nt < 16; nt++) {
            float p0 = __expf(Sacc[nt].x - mn0);
            float p1 = __expf(Sacc[nt].y - mn0);
            float p2 = __expf(Sacc[nt].z - mn1);
            float p3 = __expf(Sacc[nt].w - mn1);
            s0 += p0 + p1; s1 += p2 + p3;
            PH01[nt] = pack_hi(p0, p1); PL01[nt] = pack_lo(p0, p1, PH01[nt]);
            PH23[nt] = pack_hi(p2, p3); PL23[nt] = pack_lo(p2, p3, PH23[nt]);
        }
        s0 += __shfl_xor_sync(0xffffffffu, s0, 1);
        s0 += __shfl_xor_sync(0xffffffffu, s0, 2);
        s1 += __shfl_xor_sync(0xffffffffu, s1, 1);
        s1 += __shfl_xor_sync(0xffffffffu, s1, 2);
        l0 = __expf(m0 - mn0) * l0 + s0;   m0 = mn0;
        l1 = __expf(m1 - mn1) * l1 + s1;   m1 = mn1;

        // ---- O += P V : A-frags come straight from packed P registers ----
#pragma unroll
        for (int s = 0; s < 8; s++) {
            uint32_t ah0 = PH01[2*s],   ah1 = PH23[2*s];
            uint32_t ah2 = PH01[2*s+1], ah3 = PH23[2*s+1];
            uint32_t al0 = PL01[2*s],   al1 = PL23[2*s];
            uint32_t al2 = PL01[2*s+1], al3 = PL23[2*s+1];
#pragma unroll
            for (int nt = 0; nt < 8; nt++) {
                int wB = vbase + nt * (8 * 68) + s * 8;
                uint32_t vh0 = sm[VHI_W + wB], vh1 = sm[VHI_W + wB + 4];
                uint32_t vl0 = sm[VLO_W + wB], vl1 = sm[VLO_W + wB + 4];
                mma16816(Oacc[nt], ah0, ah1, ah2, ah3, vh0, vh1);
                mma16816(Oacc[nt], al0, al1, al2, al3, vh0, vh1);
                mma16816(Oacc[nt], ah0, ah1, ah2, ah3, vl0, vl1);
            }
        }
    }

    // ---- epilogue: O / L, write (B,T,D) ----
    const float inv0 = 1.f / l0, inv1 = 1.f / l1;
    const int rowg = q0 + wid * 16 + r0;
    float* op0 = O + ((size_t)(b * TT) + rowg) * 1024 + h * 64 + c2;
    float* op1 = op0 + (size_t)8 * 1024;
#pragma unroll
    for (int nt = 0; nt < 8; nt++) {
        *(float2*)(op0 + nt * 8) = make_float2(Oacc[nt].x * inv0, Oacc[nt].y * inv0);
        *(float2*)(op1 + nt * 8) = make_float2(Oacc[nt].z * inv1, Oacc[nt].w * inv1);
    }
}

// ===========================================================================
extern "C" void kernel_launch(void* const* d_in, const int* in_sizes, int n_in,
                              void* d_out, int out_size)
{
    const float* x  = (const float*)d_in[0];
    const float* wq = (const float*)d_in[1];
    const float* bq = (const float*)d_in[2];
    const float* wk = (const float*)d_in[3];
    const float* bk = (const float*)d_in[4];
    const float* wv = (const float*)d_in[5];
    const float* bv = (const float*)d_in[6];
    const float* wo = (const float*)d_in[7];
    const float* bo = (const float*)d_in[8];
    float* out = (float*)d_out;

    float *gQ, *gK, *gVT, *gO;
    cudaGetSymbolAddress((void**)&gQ,  g_Q);
    cudaGetSymbolAddress((void**)&gK,  g_K);
    cudaGetSymbolAddress((void**)&gVT, g_VT);
    cudaGetSymbolAddress((void**)&gO,  g_O);

    cudaFuncSetAttribute(attn_mma,
                         cudaFuncAttributeMaxDynamicSharedMemorySize, SMEM_ATTN_B);

    dim3 gg(8, 128);
    gemm128<<<gg, 256>>>(x, wq, bq, gQ, 1);   // Q -> (b,h,t,d)
    gemm128<<<gg, 256>>>(x, wk, bk, gK, 1);   // K -> (b,h,t,d)
    gemm128<<<gg, 256>>>(x, wv, bv, gVT, 2);  // V -> (b,h,d,t)

    attn_mma<<<dim3(32, 64), 256, SMEM_ATTN_B>>>(gQ, gK, gVT, gO);

    gemm128<<<gg, 256>>>(gO, wo, bo, out, 0); // final projection
}

// round 4
// speedup vs baseline: 2.6205x; 2.2664x over previous
#include <cuda_runtime.h>
#include <cuda_bf16.h>
#include <math.h>
#include <cstdint>

// Problem constants
#define BB   4
#define TT   4096
#define DD   1024
#define HH   16
#define NKV  32          // TT / 128 KV blocks

// Scratch (device globals: allocation-free rule)
__device__ float g_Q [BB*HH*TT*64];   // (b,h,t,d)
__device__ float g_K [BB*HH*TT*64];   // (b,h,t,d)
__device__ float g_VT[BB*HH*64*TT];   // (b,h,d,t)  V transposed per head
__device__ float g_O [BB*TT*DD];      // (b,t,D)

// ===========================================================================
// common helpers
// ===========================================================================
__device__ __forceinline__ void mma16816(float4& d,
    uint32_t a0, uint32_t a1, uint32_t a2, uint32_t a3,
    uint32_t b0, uint32_t b1)
{
    asm volatile(
        "mma.sync.aligned.m16n8k16.row.col.f32.bf16.bf16.f32 "
        "{%0,%1,%2,%3}, {%4,%5,%6,%7}, {%8,%9}, {%0,%1,%2,%3};"
        : "+f"(d.x), "+f"(d.y), "+f"(d.z), "+f"(d.w)
        : "r"(a0), "r"(a1), "r"(a2), "r"(a3), "r"(b0), "r"(b1));
}

__device__ __forceinline__ uint32_t pack_hi(float a, float b) {
    __nv_bfloat162 t = __floats2bfloat162_rn(a, b);
    return *(uint32_t*)&t;
}
__device__ __forceinline__ uint32_t pack_lo(float a, float b, uint32_t hi) {
    __nv_bfloat162 h = *(__nv_bfloat162*)&hi;
    __nv_bfloat162 t = __floats2bfloat162_rn(a - __bfloat162float(h.x),
                                             b - __bfloat162float(h.y));
    return *(uint32_t*)&t;
}

// ===========================================================================
// bf16 hi/lo mma.sync projection GEMM
// C(16384x1024) = A @ W^T + bias.  Block 128x128, 8 warps (warp 32x64),
// K-chunks of 32. 3-term split: Ah*Wh + Ah*Wl + Al*Wh.
// mode 0: (B,T,D) row-major   mode 1: head-split (b,h,t,d)
// mode 2: head-split transposed (b,h,d,t) via smem transpose epilogue
// ===========================================================================
#define GSTR 18
#define GA_H 0
#define GA_L (128 * GSTR)
#define GW_H (2 * 128 * GSTR)
#define GW_L (3 * 128 * GSTR)
#define EP_STR 129
#define GEMM_SMEM_B (128 * EP_STR * 4)    // 66048 >= 4*128*18*4

__global__ __launch_bounds__(256)
void gemm_bf16(const float* __restrict__ A, const float* __restrict__ W,
               const float* __restrict__ bias, float* __restrict__ C, int mode)
{
    extern __shared__ uint32_t sw[];
    const int tid = threadIdx.x, lane = tid & 31, wid = tid >> 5;
    const int wm = wid >> 1, wn = wid & 1;
    const int n0 = blockIdx.x * 128, m0 = blockIdx.y * 128;
    const int r0 = lane >> 2, c2l = lane & 3;

    float4 acc[2][8];
#pragma unroll
    for (int mt = 0; mt < 2; mt++)
#pragma unroll
        for (int nt = 0; nt < 8; nt++) acc[mt][nt] = make_float4(0.f, 0.f, 0.f, 0.f);

    for (int kt = 0; kt < 1024; kt += 32) {
        __syncthreads();
#pragma unroll
        for (int it = 0; it < 4; it++) {
            int e = tid + it * 256;          // 0..1023
            int r = e >> 3, c4 = e & 7;
            int w = r * GSTR + c4 * 2;
            float4 va = *(const float4*)&A[(size_t)(m0 + r) * 1024 + kt + c4 * 4];
            uint32_t h0 = pack_hi(va.x, va.y), h1 = pack_hi(va.z, va.w);
            sw[GA_H + w] = h0;  sw[GA_H + w + 1] = h1;
            sw[GA_L + w] = pack_lo(va.x, va.y, h0);
            sw[GA_L + w + 1] = pack_lo(va.z, va.w, h1);
            float4 vw = *(const float4*)&W[(size_t)(n0 + r) * 1024 + kt + c4 * 4];
            h0 = pack_hi(vw.x, vw.y); h1 = pack_hi(vw.z, vw.w);
            sw[GW_H + w] = h0;  sw[GW_H + w + 1] = h1;
            sw[GW_L + w] = pack_lo(vw.x, vw.y, h0);
            sw[GW_L + w + 1] = pack_lo(vw.z, vw.w, h1);
        }
        __syncthreads();

#pragma unroll
        for (int ks = 0; ks < 2; ks++) {
            uint32_t AH[2][4], AL[2][4];
#pragma unroll
            for (int mt = 0; mt < 2; mt++) {
                int aw = (wm * 32 + mt * 16 + r0) * GSTR + c2l + ks * 8;
                AH[mt][0] = sw[GA_H + aw];
                AH[mt][1] = sw[GA_H + aw + 8 * GSTR];
                AH[mt][2] = sw[GA_H + aw + 4];
                AH[mt][3] = sw[GA_H + aw + 8 * GSTR + 4];
                AL[mt][0] = sw[GA_L + aw];
                AL[mt][1] = sw[GA_L + aw + 8 * GSTR];
                AL[mt][2] = sw[GA_L + aw + 4];
                AL[mt][3] = sw[GA_L + aw + 8 * GSTR + 4];
            }
#pragma unroll
            for (int nt = 0; nt < 8; nt++) {
                int bw = (wn * 64 + nt * 8 + r0) * GSTR + c2l + ks * 8;
                uint32_t bh0 = sw[GW_H + bw], bh1 = sw[GW_H + bw + 4];
                uint32_t bl0 = sw[GW_L + bw], bl1 = sw[GW_L + bw + 4];
#pragma unroll
                for (int mt = 0; mt < 2; mt++) {
                    mma16816(acc[mt][nt], AH[mt][0], AH[mt][1], AH[mt][2], AH[mt][3], bh0, bh1);
                    mma16816(acc[mt][nt], AL[mt][0], AL[mt][1], AL[mt][2], AL[mt][3], bh0, bh1);
                    mma16816(acc[mt][nt], AH[mt][0], AH[mt][1], AH[mt][2], AH[mt][3], bl0, bl1);
                }
            }
        }
    }

    // ---- epilogue ----
    if (mode != 2) {
#pragma unroll
        for (int mt = 0; mt < 2; mt++) {
            int rowa = wm * 32 + mt * 16 + r0;
#pragma unroll
            for (int nt = 0; nt < 8; nt++) {
                int col = wn * 64 + nt * 8 + c2l * 2;
                float b0 = bias[n0 + col], b1 = bias[n0 + col + 1];
                float2 v0 = make_float2(acc[mt][nt].x + b0, acc[mt][nt].y + b1);
                float2 v1 = make_float2(acc[mt][nt].z + b0, acc[mt][nt].w + b1);
                if (mode == 0) {
                    *(float2*)&C[(size_t)(m0 + rowa) * 1024 + n0 + col] = v0;
                    *(float2*)&C[(size_t)(m0 + rowa + 8) * 1024 + n0 + col] = v1;
                } else {
                    int n = n0 + col, h = n >> 6, dcol = n & 63;
                    int ma = m0 + rowa;
                    int ba = ma >> 12, ta = ma & 4095;
                    *(float2*)&C[(((size_t)(ba * 16 + h) * 4096 + ta) * 64) + dcol] = v0;
                    *(float2*)&C[(((size_t)(ba * 16 + h) * 4096 + ta + 8) * 64) + dcol] = v1;
                }
            }
        }
    } else {
        __syncthreads();
        float* sf = (float*)sw;
#pragma unroll
        for (int mt = 0; mt < 2; mt++) {
            int rowa = wm * 32 + mt * 16 + r0;
#pragma unroll
            for (int nt = 0; nt < 8; nt++) {
                int col = wn * 64 + nt * 8 + c2l * 2;
                float b0 = bias[n0 + col], b1 = bias[n0 + col + 1];
                sf[rowa * EP_STR + col]           = acc[mt][nt].x + b0;
                sf[rowa * EP_STR + col + 1]       = acc[mt][nt].y + b1;
                sf[(rowa + 8) * EP_STR + col]     = acc[mt][nt].z + b0;
                sf[(rowa + 8) * EP_STR + col + 1] = acc[mt][nt].w + b1;
            }
        }
        __syncthreads();
        const int ba = m0 >> 12, t0 = m0 & 4095;
#pragma unroll
        for (int it = 0; it < 16; it++) {
            int e = tid + it * 256;            // 0..4095
            int col = e >> 5, r4 = e & 31;
            float4 o;
            o.x = sf[(r4 * 4 + 0) * EP_STR + col];
            o.y = sf[(r4 * 4 + 1) * EP_STR + col];
            o.z = sf[(r4 * 4 + 2) * EP_STR + col];
            o.w = sf[(r4 * 4 + 3) * EP_STR + col];
            int n = n0 + col, h = n >> 6, dcol = n & 63;
            *(float4*)&C[((size_t)((ba * 16 + h) * 64 + dcol)) * 4096 + t0 + r4 * 4] = o;
        }
    }
}

// ===========================================================================
// mma.sync bf16 attention (unchanged from R3 — proven, tensor 63.7%)
// ===========================================================================
#define KHI_W 0
#define KLO_W 4608          // 128*36
#define VHI_W 9216
#define VLO_W 13568         // + 64*68
#define SMEM_W 17920
#define SMEM_ATTN_B (SMEM_W * 4)

__global__ __launch_bounds__(256, 1)
void attn_mma(const float* __restrict__ Q, const float* __restrict__ K,
              const float* __restrict__ VT, float* __restrict__ O)
{
    extern __shared__ uint32_t sm[];
    const int tid  = threadIdx.x;
    const int lane = tid & 31, wid = tid >> 5;
    const int bh = blockIdx.y, q0 = blockIdx.x * 128;
    const int b = bh >> 4, h = bh & 15;

    const int r0 = lane >> 2;
    const int c2 = (lane & 3) * 2;

    uint32_t QH[16], QL[16];
    {
        const float* gq = Q + ((size_t)bh * TT + q0 + wid * 16) * 64;
#pragma unroll
        for (int ks = 0; ks < 4; ks++)
#pragma unroll
            for (int ko = 0; ko < 2; ko++)
#pragma unroll
                for (int ro = 0; ro < 2; ro++) {
                    float2 q = *(const float2*)(gq + (size_t)(r0 + 8 * ro) * 64
                                                + ks * 16 + ko * 8 + c2);
                    int idx = ks * 4 + ko * 2 + ro;
                    QH[idx] = pack_hi(q.x, q.y);
                    QL[idx] = pack_lo(q.x, q.y, QH[idx]);
                }
    }

    float4 Oacc[8];
#pragma unroll
    for (int i = 0; i < 8; i++) Oacc[i] = make_float4(0.f, 0.f, 0.f, 0.f);
    float m0 = -INFINITY, m1 = -INFINITY, l0 = 0.f, l1 = 0.f;

    const int kbase = (lane >> 2) * 36 + (lane & 3);
    const int vbase = (lane >> 2) * 68 + (lane & 3);

    for (int j = 0; j < NKV; j++) {
        __syncthreads();
        {
            const float* gk = K + ((size_t)bh * TT + j * 128) * 64;
#pragma unroll
            for (int it = 0; it < 8; it++) {
                int e = tid + it * 256;
                int r = e >> 4, c4 = e & 15;
                float4 v = ((const float4*)gk)[e];
                int w = r * 36 + c4 * 2;
                uint32_t h0 = pack_hi(v.x, v.y), h1 = pack_hi(v.z, v.w);
                sm[KHI_W + w] = h0;           sm[KHI_W + w + 1] = h1;
                sm[KLO_W + w] = pack_lo(v.x, v.y, h0);
                sm[KLO_W + w + 1] = pack_lo(v.z, v.w, h1);
            }
            const float* gv = VT + (size_t)bh * 64 * TT + j * 128;
#pragma unroll
            for (int it = 0; it < 8; it++) {
                int e = tid + it * 256;
                int r = e >> 5, c4 = e & 31;
                float4 v = *(const float4*)(gv + (size_t)r * TT + c4 * 4);
                int w = r * 68 + c4 * 2;
                uint32_t h0 = pack_hi(v.x, v.y), h1 = pack_hi(v.z, v.w);
                sm[VHI_W + w] = h0;           sm[VHI_W + w + 1] = h1;
                sm[VLO_W + w] = pack_lo(v.x, v.y, h0);
                sm[VLO_W + w + 1] = pack_lo(v.z, v.w, h1);
            }
        }
        __syncthreads();

        float4 Sacc[16];
#pragma unroll
        for (int nt = 0; nt < 16; nt++) {
            float4 acc = make_float4(0.f, 0.f, 0.f, 0.f);
            int nb = nt * (8 * 36);
#pragma unroll
            for (int ks = 0; ks < 4; ks++) {
                int wA = kbase + nb + ks * 8;
                uint32_t bh0 = sm[KHI_W + wA], bh1 = sm[KHI_W + wA + 4];
                uint32_t bl0 = sm[KLO_W + wA], bl1 = sm[KLO_W + wA + 4];
                int q = ks * 4;
                mma16816(acc, QH[q], QH[q+1], QH[q+2], QH[q+3], bh0, bh1);
                mma16816(acc, QH[q], QH[q+1], QH[q+2], QH[q+3], bl0, bl1);
                mma16816(acc, QL[q], QL[q+1], QL[q+2], QL[q+3], bh0, bh1);
            }
            Sacc[nt] = acc;
        }

        float mx0 = -INFINITY, mx1 = -INFINITY;
#pragma unroll
        for (int nt = 0; nt < 16; nt++) {
            mx0 = fmaxf(mx0, fmaxf(Sacc[nt].x, Sacc[nt].y));
            mx1 = fmaxf(mx1, fmaxf(Sacc[nt].z, Sacc[nt].w));
        }
        mx0 = fmaxf(mx0, __shfl_xor_sync(0xffffffffu, mx0, 1));
        mx0 = fmaxf(mx0, __shfl_xor_sync(0xffffffffu, mx0, 2));
        mx1 = fmaxf(mx1, __shfl_xor_sync(0xffffffffu, mx1, 1));
        mx1 = fmaxf(mx1, __shfl_xor_sync(0xffffffffu, mx1, 2));
        float mn0 = fmaxf(m0, mx0), mn1 = fmaxf(m1, mx1);

        uint32_t PH01[16], PH23[16], PL01[16], PL23[16];
        float s0 = 0.f, s1 = 0.f;
#pragma unroll
        for (int nt = 0; nt < 16; nt++) {
            float p0 = __expf(Sacc[nt].x - mn0);
            float p1 = __expf(Sacc[nt].y - mn0);
            float p2 = __expf(Sacc[nt].z - mn1);
            float p3 = __expf(Sacc[nt].w - mn1);
            s0 += p0 + p1; s1 += p2 + p3;
            PH01[nt] = pack_hi(p0, p1); PL01[nt] = pack_lo(p0, p1, PH01[nt]);
            PH23[nt] = pack_hi(p2, p3); PL23[nt] = pack_lo(p2, p3, PH23[nt]);
        }
        s0 += __shfl_xor_sync(0xffffffffu, s0, 1);
        s0 += __shfl_xor_sync(0xffffffffu, s0, 2);
        s1 += __shfl_xor_sync(0xffffffffu, s1, 1);
        s1 += __shfl_xor_sync(0xffffffffu, s1, 2);
        l0 = __expf(m0 - mn0) * l0 + s0;   m0 = mn0;
        l1 = __expf(m1 - mn1) * l1 + s1;   m1 = mn1;

#pragma unroll
        for (int s = 0; s < 8; s++) {
            uint32_t ah0 = PH01[2*s],   ah1 = PH23[2*s];
            uint32_t ah2 = PH01[2*s+1], ah3 = PH23[2*s+1];
            uint32_t al0 = PL01[2*s],   al1 = PL23[2*s];
            uint32_t al2 = PL01[2*s+1], al3 = PL23[2*s+1];
#pragma unroll
            for (int nt = 0; nt < 8; nt++) {
                int wB = vbase + nt * (8 * 68) + s * 8;
                uint32_t vh0 = sm[VHI_W + wB], vh1 = sm[VHI_W + wB + 4];
                uint32_t vl0 = sm[VLO_W + wB], vl1 = sm[VLO_W + wB + 4];
                mma16816(Oacc[nt], ah0, ah1, ah2, ah3, vh0, vh1);
                mma16816(Oacc[nt], al0, al1, al2, al3, vh0, vh1);
                mma16816(Oacc[nt], ah0, ah1, ah2, ah3, vl0, vl1);
            }
        }
    }

    const float inv0 = 1.f / l0, inv1 = 1.f / l1;
    const int rowg = q0 + wid * 16 + r0;
    float* op0 = O + ((size_t)(b * TT) + rowg) * 1024 + h * 64 + c2;
    float* op1 = op0 + (size_t)8 * 1024;
#pragma unroll
    for (int nt = 0; nt < 8; nt++) {
        *(float2*)(op0 + nt * 8) = make_float2(Oacc[nt].x * inv0, Oacc[nt].y * inv0);
        *(float2*)(op1 + nt * 8) = make_float2(Oacc[nt].z * inv1, Oacc[nt].w * inv1);
    }
}

// ===========================================================================
extern "C" void kernel_launch(void* const* d_in, const int* in_sizes, int n_in,
                              void* d_out, int out_size)
{
    const float* x  = (const float*)d_in[0];
    const float* wq = (const float*)d_in[1];
    const float* bq = (const float*)d_in[2];
    const float* wk = (const float*)d_in[3];
    const float* bk = (const float*)d_in[4];
    const float* wv = (const float*)d_in[5];
    const float* bv = (const float*)d_in[6];
    const float* wo = (const float*)d_in[7];
    const float* bo = (const float*)d_in[8];
    float* out = (float*)d_out;

    float *gQ, *gK, *gVT, *gO;
    cudaGetSymbolAddress((void**)&gQ,  g_Q);
    cudaGetSymbolAddress((void**)&gK,  g_K);
    cudaGetSymbolAddress((void**)&gVT, g_VT);
    cudaGetSymbolAddress((void**)&gO,  g_O);

    cudaFuncSetAttribute(attn_mma,
                         cudaFuncAttributeMaxDynamicSharedMemorySize, SMEM_ATTN_B);
    cudaFuncSetAttribute(gemm_bf16,
                         cudaFuncAttributeMaxDynamicSharedMemorySize, GEMM_SMEM_B);

    dim3 gg(8, 128);
    gemm_bf16<<<gg, 256, GEMM_SMEM_B>>>(x, wq, bq, gQ, 1);   // Q -> (b,h,t,d)
    gemm_bf16<<<gg, 256, GEMM_SMEM_B>>>(x, wk, bk, gK, 1);   // K -> (b,h,t,d)
    gemm_bf16<<<gg, 256, GEMM_SMEM_B>>>(x, wv, bv, gVT, 2);  // V -> (b,h,d,t)

    attn_mma<<<dim3(32, 64), 256, SMEM_ATTN_B>>>(gQ, gK, gVT, gO);

    gemm_bf16<<<gg, 256, GEMM_SMEM_B>>>(gO, wo, bo, out, 0); // final projection
}

// round 5
// speedup vs baseline: 3.1420x; 1.1990x over previous
#include <cuda_runtime.h>
#include <cuda_bf16.h>
#include <math.h>
#include <cstdint>

#define BB   4
#define TT   4096
#define DD   1024
#define HH   16
#define NKV  32

// ---- device scratch (uint32 = bf16x2 words) ----
__device__ uint32_t g_xh [16384 * 512];
__device__ uint32_t g_xl [16384 * 512];
__device__ uint32_t g_wh [4][1024 * 512];   // wq, wk, wv, wo (hi)
__device__ uint32_t g_wl [4][1024 * 512];   // (lo)
__device__ uint32_t g_Qh [64 * 4096 * 32];  // (b,h,t,d/2)
__device__ uint32_t g_Ql [64 * 4096 * 32];
__device__ uint32_t g_Kh [64 * 4096 * 32];
__device__ uint32_t g_Kl [64 * 4096 * 32];
__device__ uint32_t g_Vh [64 * 64 * 2048];  // (b,h,d,t/2) transposed
__device__ uint32_t g_Vl [64 * 64 * 2048];
__device__ uint32_t g_Oh [4 * 4096 * 512];  // (b,t,D/2)
__device__ uint32_t g_Ol [4 * 4096 * 512];

// ===========================================================================
// helpers
// ===========================================================================
__device__ __forceinline__ uint32_t smem_u32(const void* p) {
    uint32_t a;
    asm("{ .reg .u64 t; cvta.to.shared.u64 t, %1; cvt.u32.u64 %0, t; }"
        : "=r"(a) : "l"(p));
    return a;
}
__device__ __forceinline__ void cp16(uint32_t dst, const void* src) {
    asm volatile("cp.async.cg.shared.global [%0], [%1], 16;" :: "r"(dst), "l"(src));
}
#define CP_COMMIT() asm volatile("cp.async.commit_group;" ::: "memory")
#define CP_WAIT0()  asm volatile("cp.async.wait_group 0;" ::: "memory")

__device__ __forceinline__ void mma16816(float4& d,
    uint32_t a0, uint32_t a1, uint32_t a2, uint32_t a3,
    uint32_t b0, uint32_t b1)
{
    asm volatile(
        "mma.sync.aligned.m16n8k16.row.col.f32.bf16.bf16.f32 "
        "{%0,%1,%2,%3}, {%4,%5,%6,%7}, {%8,%9}, {%0,%1,%2,%3};"
        : "+f"(d.x), "+f"(d.y), "+f"(d.z), "+f"(d.w)
        : "r"(a0), "r"(a1), "r"(a2), "r"(a3), "r"(b0), "r"(b1));
}
__device__ __forceinline__ uint32_t pack_hi(float a, float b) {
    __nv_bfloat162 t = __floats2bfloat162_rn(a, b);
    return *(uint32_t*)&t;
}
__device__ __forceinline__ uint32_t pack_lo(float a, float b, uint32_t hi) {
    __nv_bfloat162 h = *(__nv_bfloat162*)&hi;
    __nv_bfloat162 t = __floats2bfloat162_rn(a - __bfloat162float(h.x),
                                             b - __bfloat162float(h.y));
    return *(uint32_t*)&t;
}

// ===========================================================================
// fp32 -> bf16 hi/lo split (run once per tensor)
// ===========================================================================
__global__ void cvt_hl(const float4* __restrict__ src, uint2* __restrict__ h,
                       uint2* __restrict__ l, int n4)
{
    int i = blockIdx.x * 256 + threadIdx.x;
    if (i >= n4) return;
    float4 v = src[i];
    uint32_t h0 = pack_hi(v.x, v.y), h1 = pack_hi(v.z, v.w);
    h[i] = make_uint2(h0, h1);
    l[i] = make_uint2(pack_lo(v.x, v.y, h0), pack_lo(v.z, v.w, h1));
}

// ===========================================================================
// bf16 hi/lo GEMM, pure cp.async + double buffer.
// C(16384x1024) = A @ W^T + bias.  Block 128x128, 8 warps, K-chunks of 32.
// mode 0: f32 (B,T,D)   mode 1: bf16 h/l head-split (b,h,t,d)
// mode 2: bf16 h/l head-split transposed (b,h,d,t)
// ===========================================================================
#define GSTR 20
#define GA_H 0
#define GA_L 2560
#define GW_H 5120
#define GW_L 7680
#define GBUF 10240
#define EP_STR 129
#define GEMM_SMEM_B (2 * GBUF * 4)   // 81920 >= 128*129*4 epilogue

__global__ __launch_bounds__(256, 2)
void gemm_bf16(const uint32_t* __restrict__ Ah, const uint32_t* __restrict__ Al,
               const uint32_t* __restrict__ Wh, const uint32_t* __restrict__ Wl,
               const float* __restrict__ bias,
               float* __restrict__ C0, uint32_t* __restrict__ Ch,
               uint32_t* __restrict__ Cl, int mode)
{
    extern __shared__ uint32_t sw[];
    const uint32_t sbase = smem_u32(sw);
    const int tid = threadIdx.x, lane = tid & 31, wid = tid >> 5;
    const int wm = wid >> 1, wn = wid & 1;
    const int n0 = blockIdx.x * 128, m0 = blockIdx.y * 128;
    const int r0 = lane >> 2, c2l = lane & 3;

    auto fill = [&](int buf, int kt) {
#pragma unroll
        for (int it = 0; it < 8; it++) {
            int e = tid + it * 256;
            int arr = e >> 9;                 // const per it
            int c = e & 511, row = c >> 2, cw = (c & 3) * 4;
            const uint32_t* g = (arr == 0) ? Ah : (arr == 1) ? Al
                              : (arr == 2) ? Wh : Wl;
            int rbase = (arr < 2) ? m0 : n0;
            uint32_t dw = (uint32_t)(buf * GBUF + arr * 2560 + row * GSTR + cw);
            cp16(sbase + dw * 4, g + (size_t)(rbase + row) * 512 + (kt >> 1) + cw);
        }
    };

    float4 acc[2][8];
#pragma unroll
    for (int mt = 0; mt < 2; mt++)
#pragma unroll
        for (int nt = 0; nt < 8; nt++) acc[mt][nt] = make_float4(0.f, 0.f, 0.f, 0.f);

    fill(0, 0); CP_COMMIT();

    for (int kc = 0; kc < 32; kc++) {
        CP_WAIT0();
        __syncthreads();
        if (kc + 1 < 32) fill((kc + 1) & 1, (kc + 1) * 32);
        CP_COMMIT();
        const uint32_t* sb = sw + (kc & 1) * GBUF;

#pragma unroll
        for (int ks = 0; ks < 2; ks++) {
            uint32_t AH[2][4], AL[2][4];
#pragma unroll
            for (int mt = 0; mt < 2; mt++) {
                int aw = (wm * 32 + mt * 16 + r0) * GSTR + c2l + ks * 8;
                AH[mt][0] = sb[GA_H + aw];
                AH[mt][1] = sb[GA_H + aw + 8 * GSTR];
                AH[mt][2] = sb[GA_H + aw + 4];
                AH[mt][3] = sb[GA_H + aw + 8 * GSTR + 4];
                AL[mt][0] = sb[GA_L + aw];
                AL[mt][1] = sb[GA_L + aw + 8 * GSTR];
                AL[mt][2] = sb[GA_L + aw + 4];
                AL[mt][3] = sb[GA_L + aw + 8 * GSTR + 4];
            }
#pragma unroll
            for (int nt = 0; nt < 8; nt++) {
                int bw = (wn * 64 + nt * 8 + r0) * GSTR + c2l + ks * 8;
                uint32_t bh0 = sb[GW_H + bw], bh1 = sb[GW_H + bw + 4];
                uint32_t bl0 = sb[GW_L + bw], bl1 = sb[GW_L + bw + 4];
#pragma unroll
                for (int mt = 0; mt < 2; mt++) {
                    mma16816(acc[mt][nt], AH[mt][0], AH[mt][1], AH[mt][2], AH[mt][3], bh0, bh1);
                    mma16816(acc[mt][nt], AL[mt][0], AL[mt][1], AL[mt][2], AL[mt][3], bh0, bh1);
                    mma16816(acc[mt][nt], AH[mt][0], AH[mt][1], AH[mt][2], AH[mt][3], bl0, bl1);
                }
            }
        }
        __syncthreads();
    }

    // ---- epilogue ----
    if (mode == 0) {
#pragma unroll
        for (int mt = 0; mt < 2; mt++) {
            int rowa = wm * 32 + mt * 16 + r0;
#pragma unroll
            for (int nt = 0; nt < 8; nt++) {
                int col = wn * 64 + nt * 8 + c2l * 2;
                float b0 = bias[n0 + col], b1 = bias[n0 + col + 1];
                *(float2*)&C0[(size_t)(m0 + rowa) * 1024 + n0 + col] =
                    make_float2(acc[mt][nt].x + b0, acc[mt][nt].y + b1);
                *(float2*)&C0[(size_t)(m0 + rowa + 8) * 1024 + n0 + col] =
                    make_float2(acc[mt][nt].z + b0, acc[mt][nt].w + b1);
            }
        }
    } else if (mode == 1) {
#pragma unroll
        for (int mt = 0; mt < 2; mt++) {
            int rowa = wm * 32 + mt * 16 + r0;
            int ma = m0 + rowa;
            int ba = ma >> 12, ta = ma & 4095;
#pragma unroll
            for (int nt = 0; nt < 8; nt++) {
                int col = wn * 64 + nt * 8 + c2l * 2;
                int n = n0 + col, hh = n >> 6, dcol = n & 63;
                float b0 = bias[n], b1 = bias[n + 1];
                float v0x = acc[mt][nt].x + b0, v0y = acc[mt][nt].y + b1;
                float v1x = acc[mt][nt].z + b0, v1y = acc[mt][nt].w + b1;
                size_t w0 = ((size_t)(ba * 16 + hh) * 4096 + ta) * 32 + (dcol >> 1);
                uint32_t hw = pack_hi(v0x, v0y);
                Ch[w0] = hw;  Cl[w0] = pack_lo(v0x, v0y, hw);
                hw = pack_hi(v1x, v1y);
                Ch[w0 + 8 * 32] = hw;  Cl[w0 + 8 * 32] = pack_lo(v1x, v1y, hw);
            }
        }
    } else {
        __syncthreads();
        float* sf = (float*)sw;
#pragma unroll
        for (int mt = 0; mt < 2; mt++) {
            int rowa = wm * 32 + mt * 16 + r0;
#pragma unroll
            for (int nt = 0; nt < 8; nt++) {
                int col = wn * 64 + nt * 8 + c2l * 2;
                float b0 = bias[n0 + col], b1 = bias[n0 + col + 1];
                sf[rowa * EP_STR + col]           = acc[mt][nt].x + b0;
                sf[rowa * EP_STR + col + 1]       = acc[mt][nt].y + b1;
                sf[(rowa + 8) * EP_STR + col]     = acc[mt][nt].z + b0;
                sf[(rowa + 8) * EP_STR + col + 1] = acc[mt][nt].w + b1;
            }
        }
        __syncthreads();
        const int ba = m0 >> 12, t0 = m0 & 4095;
#pragma unroll
        for (int it = 0; it < 16; it++) {
            int e = tid + it * 256;            // 0..4095
            int col = e >> 5, r4 = e & 31;
            float o0 = sf[(r4 * 4 + 0) * EP_STR + col];
            float o1 = sf[(r4 * 4 + 1) * EP_STR + col];
            float o2 = sf[(r4 * 4 + 2) * EP_STR + col];
            float o3 = sf[(r4 * 4 + 3) * EP_STR + col];
            int n = n0 + col, hh = n >> 6, dcol = n & 63;
            size_t w = ((size_t)((ba * 16 + hh) * 64 + dcol)) * 2048 + (t0 >> 1) + r4 * 2;
            uint32_t h0 = pack_hi(o0, o1), h1 = pack_hi(o2, o3);
            *(uint2*)&Ch[w] = make_uint2(h0, h1);
            *(uint2*)&Cl[w] = make_uint2(pack_lo(o0, o1, h0), pack_lo(o2, o3, h1));
        }
    }
}

// ===========================================================================
// attention: preconverted bf16 hi/lo inputs, cp.async double buffer.
// One CTA = 128 q rows of one (b,h); 8 warps; P in registers; O never rescaled.
// ===========================================================================
#define KHI_W 0
#define KLO_W 4608          // 128*36
#define VHI_W 9216
#define VLO_W 13568         // + 64*68
#define ABUF  17920
#define SMEM_ATTN_B (2 * ABUF * 4)   // 143360

__global__ __launch_bounds__(256, 1)
void attn_mma(const uint32_t* __restrict__ Qh, const uint32_t* __restrict__ Ql,
              const uint32_t* __restrict__ Kh, const uint32_t* __restrict__ Kl,
              const uint32_t* __restrict__ Vh, const uint32_t* __restrict__ Vl,
              uint32_t* __restrict__ Oh, uint32_t* __restrict__ Ol)
{
    extern __shared__ uint32_t sm[];
    const uint32_t sbase = smem_u32(sm);
    const int tid  = threadIdx.x;
    const int lane = tid & 31, wid = tid >> 5;
    const int bh = blockIdx.y, q0 = blockIdx.x * 128;
    const int b = bh >> 4, h = bh & 15;
    const int r0 = lane >> 2;

    auto fill = [&](int buf, int j) {
#pragma unroll
        for (int it = 0; it < 16; it++) {
            int e = tid + it * 256;
            if (it < 8) {                        // K: 2048 chunks
                int arr = e >> 10;               // 0 hi, 1 lo (const per it)
                int c = e & 1023, row = c >> 3, cw = (c & 7) * 4;
                const uint32_t* g = arr ? Kl : Kh;
                uint32_t dw = (uint32_t)(buf * ABUF + arr * 4608 + row * 36 + cw);
                cp16(sbase + dw * 4,
                     g + ((size_t)bh * 4096 + j * 128 + row) * 32 + cw);
            } else {                             // V: 2048 chunks
                int e2 = e - 2048;
                int arr = e2 >> 10;
                int c = e2 & 1023, row = c >> 4, cw = (c & 15) * 4;
                const uint32_t* g = arr ? Vl : Vh;
                uint32_t dw = (uint32_t)(buf * ABUF + 9216 + arr * 4352 + row * 68 + cw);
                cp16(sbase + dw * 4,
                     g + ((size_t)bh * 64 + row) * 2048 + j * 64 + cw);
            }
        }
    };

    // Q fragments straight from preconverted gmem
    uint32_t QH[16], QL[16];
    {
        const uint32_t* gqh = Qh + ((size_t)bh * 4096 + q0 + wid * 16) * 32;
        const uint32_t* gql = Ql + ((size_t)bh * 4096 + q0 + wid * 16) * 32;
#pragma unroll
        for (int ks = 0; ks < 4; ks++)
#pragma unroll
            for (int ko = 0; ko < 2; ko++)
#pragma unroll
                for (int ro = 0; ro < 2; ro++) {
                    int off = (r0 + 8 * ro) * 32 + ks * 8 + ko * 4 + (lane & 3);
                    int idx = ks * 4 + ko * 2 + ro;
                    QH[idx] = gqh[off];
                    QL[idx] = gql[off];
                }
    }

    float4 Oacc[8];
#pragma unroll
    for (int i = 0; i < 8; i++) Oacc[i] = make_float4(0.f, 0.f, 0.f, 0.f);
    float m0 = -INFINITY, m1 = -INFINITY, l0 = 0.f, l1 = 0.f;

    const int kbase = (lane >> 2) * 36 + (lane & 3);
    const int vbase = (lane >> 2) * 68 + (lane & 3);

    fill(0, 0); CP_COMMIT();

    for (int j = 0; j < NKV; j++) {
        CP_WAIT0();
        __syncthreads();
        if (j + 1 < NKV) fill((j + 1) & 1, j + 1);
        CP_COMMIT();
        const uint32_t* sb = sm + (j & 1) * ABUF;

        // ---- S = Q K^T ----
        float4 Sacc[16];
#pragma unroll
        for (int nt = 0; nt < 16; nt++) {
            float4 acc = make_float4(0.f, 0.f, 0.f, 0.f);
            int nb = nt * (8 * 36);
#pragma unroll
            for (int ks = 0; ks < 4; ks++) {
                int wA = kbase + nb + ks * 8;
                uint32_t bh0 = sb[KHI_W + wA], bh1 = sb[KHI_W + wA + 4];
                uint32_t bl0 = sb[KLO_W + wA], bl1 = sb[KLO_W + wA + 4];
                int q = ks * 4;
                mma16816(acc, QH[q], QH[q+1], QH[q+2], QH[q+3], bh0, bh1);
                mma16816(acc, QH[q], QH[q+1], QH[q+2], QH[q+3], bl0, bl1);
                mma16816(acc, QL[q], QL[q+1], QL[q+2], QL[q+3], bh0, bh1);
            }
            Sacc[nt] = acc;
        }

        // ---- streaming softmax (reference: O never rescaled) ----
        float mx0 = -INFINITY, mx1 = -INFINITY;
#pragma unroll
        for (int nt = 0; nt < 16; nt++) {
            mx0 = fmaxf(mx0, fmaxf(Sacc[nt].x, Sacc[nt].y));
            mx1 = fmaxf(mx1, fmaxf(Sacc[nt].z, Sacc[nt].w));
        }
        mx0 = fmaxf(mx0, __shfl_xor_sync(0xffffffffu, mx0, 1));
        mx0 = fmaxf(mx0, __shfl_xor_sync(0xffffffffu, mx0, 2));
        mx1 = fmaxf(mx1, __shfl_xor_sync(0xffffffffu, mx1, 1));
        mx1 = fmaxf(mx1, __shfl_xor_sync(0xffffffffu, mx1, 2));
        float mn0 = fmaxf(m0, mx0), mn1 = fmaxf(m1, mx1);

        uint32_t PH01[16], PH23[16], PL01[16], PL23[16];
        float s0 = 0.f, s1 = 0.f;
#pragma unroll
        for (int nt = 0; nt < 16; nt++) {
            float p0 = __expf(Sacc[nt].x - mn0);
            float p1 = __expf(Sacc[nt].y - mn0);
            float p2 = __expf(Sacc[nt].z - mn1);
            float p3 = __expf(Sacc[nt].w - mn1);
            s0 += p0 + p1; s1 += p2 + p3;
            PH01[nt] = pack_hi(p0, p1); PL01[nt] = pack_lo(p0, p1, PH01[nt]);
            PH23[nt] = pack_hi(p2, p3); PL23[nt] = pack_lo(p2, p3, PH23[nt]);
        }
        s0 += __shfl_xor_sync(0xffffffffu, s0, 1);
        s0 += __shfl_xor_sync(0xffffffffu, s0, 2);
        s1 += __shfl_xor_sync(0xffffffffu, s1, 1);
        s1 += __shfl_xor_sync(0xffffffffu, s1, 2);
        l0 = __expf(m0 - mn0) * l0 + s0;   m0 = mn0;
        l1 = __expf(m1 - mn1) * l1 + s1;   m1 = mn1;

        // ---- O += P V ----
#pragma unroll
        for (int s = 0; s < 8; s++) {
            uint32_t ah0 = PH01[2*s],   ah1 = PH23[2*s];
            uint32_t ah2 = PH01[2*s+1], ah3 = PH23[2*s+1];
            uint32_t al0 = PL01[2*s],   al1 = PL23[2*s];
            uint32_t al2 = PL01[2*s+1], al3 = PL23[2*s+1];
#pragma unroll
            for (int nt = 0; nt < 8; nt++) {
                int wB = vbase + nt * (8 * 68) + s * 8;
                uint32_t vh0 = sb[VHI_W + wB], vh1 = sb[VHI_W + wB + 4];
                uint32_t vl0 = sb[VLO_W + wB], vl1 = sb[VLO_W + wB + 4];
                mma16816(Oacc[nt], ah0, ah1, ah2, ah3, vh0, vh1);
                mma16816(Oacc[nt], al0, al1, al2, al3, vh0, vh1);
                mma16816(Oacc[nt], ah0, ah1, ah2, ah3, vl0, vl1);
            }
        }
        __syncthreads();
    }

    // ---- epilogue: O / L -> bf16 hi/lo in (b,t,D) ----
    const float inv0 = 1.f / l0, inv1 = 1.f / l1;
    const int rowg = q0 + wid * 16 + r0;
    uint32_t* oh = Oh + ((size_t)b * 4096 + rowg) * 512 + h * 32 + (lane & 3);
    uint32_t* ol = Ol + ((size_t)b * 4096 + rowg) * 512 + h * 32 + (lane & 3);
#pragma unroll
    for (int nt = 0; nt < 8; nt++) {
        float ax = Oacc[nt].x * inv0, ay = Oacc[nt].y * inv0;
        uint32_t hw = pack_hi(ax, ay);
        oh[nt * 4] = hw;  ol[nt * 4] = pack_lo(ax, ay, hw);
        float az = Oacc[nt].z * inv1, aw = Oacc[nt].w * inv1;
        hw = pack_hi(az, aw);
        oh[nt * 4 + 8 * 512] = hw;  ol[nt * 4 + 8 * 512] = pack_lo(az, aw, hw);
    }
}

// ===========================================================================
extern "C" void kernel_launch(void* const* d_in, const int* in_sizes, int n_in,
                              void* d_out, int out_size)
{
    const float* x  = (const float*)d_in[0];
    const float* wq = (const float*)d_in[1];
    const float* bq = (const float*)d_in[2];
    const float* wk = (const float*)d_in[3];
    const float* bk = (const float*)d_in[4];
    const float* wv = (const float*)d_in[5];
    const float* bv = (const float*)d_in[6];
    const float* wo = (const float*)d_in[7];
    const float* bo = (const float*)d_in[8];
    float* out = (float*)d_out;

    uint32_t *xh, *xl, *wh, *wl, *Qh, *Ql, *Kh, *Kl, *Vh, *Vl, *Ohp, *Olp;
    cudaGetSymbolAddress((void**)&xh, g_xh);
    cudaGetSymbolAddress((void**)&xl, g_xl);
    cudaGetSymbolAddress((void**)&wh, g_wh);
    cudaGetSymbolAddress((void**)&wl, g_wl);
    cudaGetSymbolAddress((void**)&Qh, g_Qh);
    cudaGetSymbolAddress((void**)&Ql, g_Ql);
    cudaGetSymbolAddress((void**)&Kh, g_Kh);
    cudaGetSymbolAddress((void**)&Kl, g_Kl);
    cudaGetSymbolAddress((void**)&Vh, g_Vh);
    cudaGetSymbolAddress((void**)&Vl, g_Vl);
    cudaGetSymbolAddress((void**)&Ohp, g_Oh);
    cudaGetSymbolAddress((void**)&Olp, g_Ol);

    cudaFuncSetAttribute(attn_mma,
                         cudaFuncAttributeMaxDynamicSharedMemorySize, SMEM_ATTN_B);
    cudaFuncSetAttribute(gemm_bf16,
                         cudaFuncAttributeMaxDynamicSharedMemorySize, GEMM_SMEM_B);

    const int WW = 1024 * 512;   // words per weight matrix

    // ---- one-time conversions ----
    cvt_hl<<<16384, 256>>>((const float4*)x,  (uint2*)xh, (uint2*)xl, 4194304);
    cvt_hl<<<1024, 256>>>((const float4*)wq, (uint2*)(wh + 0*WW), (uint2*)(wl + 0*WW), 262144);
    cvt_hl<<<1024, 256>>>((const float4*)wk, (uint2*)(wh + 1*WW), (uint2*)(wl + 1*WW), 262144);
    cvt_hl<<<1024, 256>>>((const float4*)wv, (uint2*)(wh + 2*WW), (uint2*)(wl + 2*WW), 262144);
    cvt_hl<<<1024, 256>>>((const float4*)wo, (uint2*)(wh + 3*WW), (uint2*)(wl + 3*WW), 262144);

    dim3 gg(8, 128);
    gemm_bf16<<<gg, 256, GEMM_SMEM_B>>>(xh, xl, wh + 0*WW, wl + 0*WW, bq,
                                        nullptr, Qh, Ql, 1);
    gemm_bf16<<<gg, 256, GEMM_SMEM_B>>>(xh, xl, wh + 1*WW, wl + 1*WW, bk,
                                        nullptr, Kh, Kl, 1);
    gemm_bf16<<<gg, 256, GEMM_SMEM_B>>>(xh, xl, wh + 2*WW, wl + 2*WW, bv,
                                        nullptr, Vh, Vl, 2);

    attn_mma<<<dim3(32, 64), 256, SMEM_ATTN_B>>>(Qh, Ql, Kh, Kl, Vh, Vl, Ohp, Olp);

    gemm_bf16<<<gg, 256, GEMM_SMEM_B>>>(Ohp, Olp, wh + 3*WW, wl + 3*WW, bo,
                                        out, nullptr, nullptr, 0);
}